// round 1
// baseline (speedup 1.0000x reference)
#include <cuda_runtime.h>
#include <math.h>

// ---------------- problem constants ----------------
#define Hdim   1024
#define Fdim   2816
#define NEXP   8
#define NTOK   4096
#define NPAIR  8192          // NTOK * TOP_K
#define BM     64
#define BN     64
#define BK     16
#define MAX_ROWS  (NPAIR + NEXP * BM)     // 8704 padded rows
#define MAX_TILES (NPAIR / BM + NEXP)     // 136 row tiles max

// ---------------- device scratch (no allocations allowed) ----------------
__device__ int   g_pair_expert[NPAIR];
__device__ float g_pair_score[NPAIR];
__device__ int   g_row_map[MAX_ROWS];     // padded row -> pair id (or -1)
__device__ int   g_tile_expert[MAX_TILES];
__device__ float g_act[(size_t)NPAIR * Fdim];   // GLU activations per pair (~92 MB)
__device__ float g_outp[(size_t)NPAIR * Hdim];  // per-pair FFN2 output (~34 MB)

// ---------------- 1) router: attention-router + top-2 ----------------
__global__ void router_kernel(const float* __restrict__ x,
                              const float* __restrict__ wqkv) {
    __shared__ float sx[Hdim];
    __shared__ float sdot[24];
    const int t = blockIdx.x;                 // token id
    const float* xr = x + (size_t)t * Hdim;
    for (int i = threadIdx.x; i < Hdim; i += blockDim.x) sx[i] = xr[i];
    __syncthreads();

    const int warp = threadIdx.x >> 5, lane = threadIdx.x & 31;
    for (int o = warp; o < 24; o += 8) {      // 8 warps, 3 dots each
        const float* w = wqkv + (size_t)o * Hdim;
        float s = 0.f;
        for (int i = lane; i < Hdim; i += 32) s += sx[i] * w[i];
        #pragma unroll
        for (int off = 16; off; off >>= 1) s += __shfl_down_sync(0xffffffffu, s, off);
        if (lane == 0) sdot[o] = s;
    }
    __syncthreads();

    if (threadIdx.x == 0) {
        float q[NEXP], k[NEXP], v[NEXP], logit[NEXP];
        #pragma unroll
        for (int e = 0; e < NEXP; e++) { q[e]=sdot[e]; k[e]=sdot[8+e]; v[e]=sdot[16+e]; }
        for (int e = 0; e < NEXP; e++) {
            float m = -1e30f;
            for (int j = 0; j < NEXP; j++) m = fmaxf(m, q[e]*k[j]);
            float se = 0.f, acc = 0.f;
            for (int j = 0; j < NEXP; j++) {
                float ex = expf(q[e]*k[j] - m);
                se += ex; acc += ex * v[j];
            }
            logit[e] = acc / se;
        }
        // top-2, ties -> lower index (jax.lax.top_k semantics)
        int i0 = 0;
        for (int j = 1; j < NEXP; j++) if (logit[j] > logit[i0]) i0 = j;
        int i1 = -1;
        for (int j = 0; j < NEXP; j++) {
            if (j == i0) continue;
            if (i1 < 0 || logit[j] > logit[i1]) i1 = j;
        }
        float e1 = expf(logit[i1] - logit[i0]);
        float inv = 1.f / (1.f + e1);
        g_pair_expert[2*t]   = i0; g_pair_score[2*t]   = inv;
        g_pair_expert[2*t+1] = i1; g_pair_score[2*t+1] = e1 * inv;
    }
}

// ---------------- 2) scheduling: per-expert padded segments ----------------
__global__ void schedule_kernel() {
    __shared__ int s_cnt[NEXP], s_off[NEXP], s_cur[NEXP];
    const int tid = threadIdx.x;
    if (tid < NEXP) { s_cnt[tid] = 0; s_cur[tid] = 0; }
    __syncthreads();
    for (int i = tid; i < MAX_ROWS; i += blockDim.x) g_row_map[i] = -1;
    for (int p = tid; p < NPAIR; p += blockDim.x)
        atomicAdd(&s_cnt[g_pair_expert[p]], 1);
    __syncthreads();
    if (tid == 0) {
        int off = 0, t = 0;
        for (int e = 0; e < NEXP; e++) {
            s_off[e] = off;
            int nt = (s_cnt[e] + BM - 1) / BM;
            for (int i = 0; i < nt; i++) g_tile_expert[t++] = e;
            off += nt * BM;
        }
        for (; t < MAX_TILES; t++) g_tile_expert[t] = -1;
    }
    __syncthreads();
    for (int p = tid; p < NPAIR; p += blockDim.x) {
        int e = g_pair_expert[p];
        int pos = atomicAdd(&s_cur[e], 1);
        g_row_map[s_off[e] + pos] = p;     // order nondeterministic; results aren't
    }
}

// ---------------- 3) FFN1: fused GLU (a & g halves), SiLU epilogue ----------------
__global__ void __launch_bounds__(256) ffn1_kernel(const float* __restrict__ x,
                                                   const float* __restrict__ w1) {
    const int tileRow = blockIdx.y;
    const int e = g_tile_expert[tileRow];
    if (e < 0) return;
    const int f0   = blockIdx.x * BN;
    const int base = tileRow * BM;

    __shared__ float As[BK][BM];
    __shared__ float Ba[BK][BN];
    __shared__ float Bg[BK][BN];

    const int tid   = threadIdx.x;
    const int loadM = tid >> 2;            // 0..63
    const int loadK = (tid & 3) << 2;      // 0,4,8,12

    const int  pA     = g_row_map[base + loadM];
    const bool aValid = (pA >= 0);
    const float* aRow = aValid ? x + (size_t)(pA >> 1) * Hdim : x;

    const float* w1e   = w1 + (size_t)e * 2 * Fdim * Hdim;
    const float* baRow = w1e + (size_t)(f0 + loadM) * Hdim;
    const float* bgRow = w1e + (size_t)(Fdim + f0 + loadM) * Hdim;

    const int tx = tid & 15, ty = tid >> 4;
    float acc_a[4][4] = {}, acc_g[4][4] = {};

    for (int k0 = 0; k0 < Hdim; k0 += BK) {
        float4 av = aValid ? *(const float4*)(aRow + k0 + loadK)
                           : make_float4(0.f, 0.f, 0.f, 0.f);
        float4 bav = *(const float4*)(baRow + k0 + loadK);
        float4 bgv = *(const float4*)(bgRow + k0 + loadK);
        __syncthreads();
        As[loadK+0][loadM]=av.x;  As[loadK+1][loadM]=av.y;  As[loadK+2][loadM]=av.z;  As[loadK+3][loadM]=av.w;
        Ba[loadK+0][loadM]=bav.x; Ba[loadK+1][loadM]=bav.y; Ba[loadK+2][loadM]=bav.z; Ba[loadK+3][loadM]=bav.w;
        Bg[loadK+0][loadM]=bgv.x; Bg[loadK+1][loadM]=bgv.y; Bg[loadK+2][loadM]=bgv.z; Bg[loadK+3][loadM]=bgv.w;
        __syncthreads();
        #pragma unroll
        for (int k = 0; k < BK; k++) {
            float4 a  = *(const float4*)&As[k][ty*4];
            float4 ba = *(const float4*)&Ba[k][tx*4];
            float4 bg = *(const float4*)&Bg[k][tx*4];
            float ar[4] = {a.x, a.y, a.z, a.w};
            float br[4] = {ba.x, ba.y, ba.z, ba.w};
            float gr[4] = {bg.x, bg.y, bg.z, bg.w};
            #pragma unroll
            for (int i = 0; i < 4; i++)
                #pragma unroll
                for (int j = 0; j < 4; j++) {
                    acc_a[i][j] += ar[i] * br[j];
                    acc_g[i][j] += ar[i] * gr[j];
                }
        }
    }
    #pragma unroll
    for (int i = 0; i < 4; i++) {
        int p = g_row_map[base + ty*4 + i];
        if (p < 0) continue;
        float* orow = g_act + (size_t)p * Fdim + f0 + tx*4;
        #pragma unroll
        for (int j = 0; j < 4; j++) {
            float a = acc_a[i][j];
            float s = a / (1.f + expf(-a));     // silu
            orow[j] = s * acc_g[i][j];
        }
    }
}

// ---------------- 4) FFN2: act @ w2[e]^T, scaled by routing score ----------------
__global__ void __launch_bounds__(256) ffn2_kernel(const float* __restrict__ w2) {
    const int tileRow = blockIdx.y;
    const int e = g_tile_expert[tileRow];
    if (e < 0) return;
    const int n0   = blockIdx.x * BN;
    const int base = tileRow * BM;

    __shared__ float As[BK][BM];
    __shared__ float Bs[BK][BN];

    const int tid   = threadIdx.x;
    const int loadM = tid >> 2;
    const int loadK = (tid & 3) << 2;

    const int  pA     = g_row_map[base + loadM];
    const bool aValid = (pA >= 0);
    const float* aRow = aValid ? g_act + (size_t)pA * Fdim : g_act;
    const float* bRow = w2 + (size_t)e * Hdim * Fdim + (size_t)(n0 + loadM) * Fdim;

    const int tx = tid & 15, ty = tid >> 4;
    float acc[4][4] = {};

    for (int k0 = 0; k0 < Fdim; k0 += BK) {
        float4 av = aValid ? *(const float4*)(aRow + k0 + loadK)
                           : make_float4(0.f, 0.f, 0.f, 0.f);
        float4 bv = *(const float4*)(bRow + k0 + loadK);
        __syncthreads();
        As[loadK+0][loadM]=av.x; As[loadK+1][loadM]=av.y; As[loadK+2][loadM]=av.z; As[loadK+3][loadM]=av.w;
        Bs[loadK+0][loadM]=bv.x; Bs[loadK+1][loadM]=bv.y; Bs[loadK+2][loadM]=bv.z; Bs[loadK+3][loadM]=bv.w;
        __syncthreads();
        #pragma unroll
        for (int k = 0; k < BK; k++) {
            float4 a = *(const float4*)&As[k][ty*4];
            float4 b = *(const float4*)&Bs[k][tx*4];
            float ar[4] = {a.x, a.y, a.z, a.w};
            float br[4] = {b.x, b.y, b.z, b.w};
            #pragma unroll
            for (int i = 0; i < 4; i++)
                #pragma unroll
                for (int j = 0; j < 4; j++)
                    acc[i][j] += ar[i] * br[j];
        }
    }
    #pragma unroll
    for (int i = 0; i < 4; i++) {
        int p = g_row_map[base + ty*4 + i];
        if (p < 0) continue;
        float sc = g_pair_score[p];
        float* orow = g_outp + (size_t)p * Hdim + n0 + tx*4;
        #pragma unroll
        for (int j = 0; j < 4; j++) orow[j] = acc[i][j] * sc;
    }
}

// ---------------- 5) combine: sum the two pair slots per token ----------------
__global__ void combine_kernel(float* __restrict__ out) {
    int i = blockIdx.x * blockDim.x + threadIdx.x;
    if (i >= NTOK * Hdim) return;
    int t = i >> 10;           // Hdim = 1024
    int j = i & 1023;
    out[i] = g_outp[(size_t)(2*t) * Hdim + j] + g_outp[(size_t)(2*t+1) * Hdim + j];
}

// ---------------- launch ----------------
extern "C" void kernel_launch(void* const* d_in, const int* in_sizes, int n_in,
                              void* d_out, int out_size) {
    const float* x    = (const float*)d_in[0];   // hidden_states (2,2048,1024)
    const float* wqkv = (const float*)d_in[1];   // (24,1024)
    const float* w1   = (const float*)d_in[2];   // (8,5632,1024)
    const float* w2   = (const float*)d_in[3];   // (8,1024,2816)
    float* out = (float*)d_out;

    router_kernel<<<NTOK, 256>>>(x, wqkv);
    schedule_kernel<<<1, 256>>>();
    dim3 g1(Fdim / BN, MAX_TILES);   // (44, 136)
    ffn1_kernel<<<g1, 256>>>(x, w1);
    dim3 g2(Hdim / BN, MAX_TILES);   // (16, 136)
    ffn2_kernel<<<g2, 256>>>(w2);
    combine_kernel<<<(NTOK * Hdim + 255) / 256, 256>>>(out);
}

// round 3
// speedup vs baseline: 2.3040x; 2.3040x over previous
#include <cuda_runtime.h>
#include <cuda_bf16.h>
#include <math.h>
#include <stdint.h>

// ---------------- problem constants ----------------
#define Hdim   1024
#define Fdim   2816
#define NCOL1  (2*Fdim)               // 5632
#define NEXP   8
#define NTOK   4096
#define NPAIR  8192
#define BM     128
#define BN     128
#define BK     32
#define NKB1   (Hdim/BK)              // 32
#define NKB2   (Fdim/BK)              // 88
#define MAX_ROWS  (NPAIR + NEXP*BM)   // 9216
#define MAX_TILES (NPAIR/BM + NEXP)   // 72

#define ROWB   80                     // 32 bf16 = 64B data, padded to 80B
#define OPERB  (128*ROWB)             // 10240 bytes per operand tile
#define STAGEB (4*OPERB)              // Ah, Al, Bh, Bl
#define NSTAGE 3
#define SMEM_TOT (512 + NSTAGE*STAGEB)   // 123392

// ---------------- device scratch ----------------
__device__ int   g_pair_expert[NPAIR];
__device__ float g_pair_score[NPAIR];
__device__ int   g_row_map[MAX_ROWS];
__device__ int   g_tile_expert[MAX_TILES];
__device__ __nv_bfloat16 g_xh[(size_t)NTOK*Hdim];
__device__ __nv_bfloat16 g_xl[(size_t)NTOK*Hdim];
__device__ __nv_bfloat16 g_w1h[(size_t)NEXP*NCOL1*Hdim];
__device__ __nv_bfloat16 g_w1l[(size_t)NEXP*NCOL1*Hdim];
__device__ __nv_bfloat16 g_w2h[(size_t)NEXP*Hdim*Fdim];
__device__ __nv_bfloat16 g_w2l[(size_t)NEXP*Hdim*Fdim];
__device__ float g_h1[(size_t)NPAIR*NCOL1];       // fp32 GLU pre-activations
__device__ __nv_bfloat16 g_acth[(size_t)NPAIR*Fdim];
__device__ __nv_bfloat16 g_actl[(size_t)NPAIR*Fdim];
__device__ float g_outp[(size_t)NPAIR*Hdim];

// ---------------- PTX helpers (sm_80-era: compile for plain sm_100) ----------------
__device__ __forceinline__ uint32_t smem_u32(const void* p){
    uint32_t a;
    asm("{ .reg .u64 t; cvta.to.shared.u64 t, %1; cvt.u32.u64 %0, t; }" : "=r"(a) : "l"(p));
    return a;
}
#define CPA(dst, src)  asm volatile("cp.async.cg.shared.global [%0], [%1], 16;" \
                                    :: "r"(dst), "l"(src))
#define CPAZ(dst, src) asm volatile("cp.async.cg.shared.global [%0], [%1], 16, %2;" \
                                    :: "r"(dst), "l"(src), "r"(0u))
#define CPCOMMIT() asm volatile("cp.async.commit_group;")
#define CPWAIT1()  asm volatile("cp.async.wait_group 1;")

#define LDSM4(R0,R1,R2,R3,ADDR) asm volatile( \
    "ldmatrix.sync.aligned.m8n8.x4.shared.b16 {%0,%1,%2,%3}, [%4];" \
    : "=r"(R0), "=r"(R1), "=r"(R2), "=r"(R3) : "r"(ADDR))

#define MMA_BF16(C, A, B0, B1) asm volatile( \
    "mma.sync.aligned.m16n8k16.row.col.f32.bf16.bf16.f32 " \
    "{%0,%1,%2,%3}, {%4,%5,%6,%7}, {%8,%9}, {%0,%1,%2,%3};" \
    : "+f"((C)[0]), "+f"((C)[1]), "+f"((C)[2]), "+f"((C)[3]) \
    : "r"((A)[0]), "r"((A)[1]), "r"((A)[2]), "r"((A)[3]), "r"(B0), "r"(B1))

// ---------------- fragment compute for one 32-wide K stage ----------------
__device__ __forceinline__ void compute_stage(uint32_t st, float c[4][4][4],
                                              uint32_t aOff, uint32_t bOff,
                                              int wm, int wn){
    #pragma unroll
    for (int ks = 0; ks < 2; ks++){
        uint32_t ah = st + 0*OPERB + (uint32_t)wm*64*ROWB + aOff + ks*32;
        uint32_t al = ah + OPERB;
        uint32_t bh = st + 2*OPERB + (uint32_t)wn*32*ROWB + bOff + ks*32;
        uint32_t bl = bh + OPERB;
        uint32_t Ah[4][4], Al[4][4], Bh[8], Bl[8];
        #pragma unroll
        for (int mi = 0; mi < 4; mi++){
            LDSM4(Ah[mi][0],Ah[mi][1],Ah[mi][2],Ah[mi][3], ah + mi*16*ROWB);
            LDSM4(Al[mi][0],Al[mi][1],Al[mi][2],Al[mi][3], al + mi*16*ROWB);
        }
        LDSM4(Bh[0],Bh[1],Bh[2],Bh[3], bh);
        LDSM4(Bh[4],Bh[5],Bh[6],Bh[7], bh + 16*ROWB);
        LDSM4(Bl[0],Bl[1],Bl[2],Bl[3], bl);
        LDSM4(Bl[4],Bl[5],Bl[6],Bl[7], bl + 16*ROWB);
        #pragma unroll
        for (int mi = 0; mi < 4; mi++)
            #pragma unroll
            for (int nj = 0; nj < 4; nj++){
                MMA_BF16(c[mi][nj], Ah[mi], Bh[nj*2], Bh[nj*2+1]);
                MMA_BF16(c[mi][nj], Ah[mi], Bl[nj*2], Bl[nj*2+1]);
                MMA_BF16(c[mi][nj], Al[mi], Bh[nj*2], Bh[nj*2+1]);
            }
    }
}

// ---------------- stage loaders ----------------
__device__ __forceinline__ void load_stage_g(uint32_t su, int s, int kb, const int* s_p,
                                             const __nv_bfloat16* Ah, const __nv_bfloat16* Al,
                                             int aShift, int aStride,
                                             const __nv_bfloat16* Bh, const __nv_bfloat16* Bl,
                                             size_t bBase, int bRow0, int bStride, int tid){
    uint32_t st = su + 512 + s*STAGEB;
    #pragma unroll
    for (int idx = tid; idx < 2048; idx += 256){
        int oper = idx >> 9;            // 0..3
        int r    = (idx >> 2) & 127;
        int c    = idx & 3;
        uint32_t dst = st + oper*OPERB + r*ROWB + c*16;
        if (oper < 2){
            int p = s_p[r];
            const __nv_bfloat16* bp = oper ? Al : Ah;
            if (p >= 0){
                const void* src = bp + (size_t)(p >> aShift)*aStride + kb*BK + c*8;
                CPA(dst, src);
            } else {
                CPAZ(dst, bp);
            }
        } else {
            const __nv_bfloat16* bp = (oper == 2) ? Bh : Bl;
            const void* src = bp + bBase + (size_t)(bRow0 + r)*bStride + kb*BK + c*8;
            CPA(dst, src);
        }
    }
}

// ---------------- 0) fp32 -> bf16 hi/lo splits ----------------
__device__ __forceinline__ void split_store(float v, __nv_bfloat16* hi, __nv_bfloat16* lo, size_t i){
    __nv_bfloat16 h = __float2bfloat16(v);
    hi[i] = h;
    lo[i] = __float2bfloat16(v - __bfloat162float(h));
}
__global__ void split_w1_kernel(const float4* __restrict__ src){
    size_t i = (size_t)blockIdx.x*blockDim.x + threadIdx.x;
    if (i >= (size_t)NEXP*NCOL1*Hdim/4) return;
    float4 v = src[i];
    split_store(v.x, g_w1h, g_w1l, 4*i+0); split_store(v.y, g_w1h, g_w1l, 4*i+1);
    split_store(v.z, g_w1h, g_w1l, 4*i+2); split_store(v.w, g_w1h, g_w1l, 4*i+3);
}
__global__ void split_w2_kernel(const float4* __restrict__ src){
    size_t i = (size_t)blockIdx.x*blockDim.x + threadIdx.x;
    if (i >= (size_t)NEXP*Hdim*Fdim/4) return;
    float4 v = src[i];
    split_store(v.x, g_w2h, g_w2l, 4*i+0); split_store(v.y, g_w2h, g_w2l, 4*i+1);
    split_store(v.z, g_w2h, g_w2l, 4*i+2); split_store(v.w, g_w2h, g_w2l, 4*i+3);
}
__global__ void split_x_kernel(const float4* __restrict__ src){
    size_t i = (size_t)blockIdx.x*blockDim.x + threadIdx.x;
    if (i >= (size_t)NTOK*Hdim/4) return;
    float4 v = src[i];
    split_store(v.x, g_xh, g_xl, 4*i+0); split_store(v.y, g_xh, g_xl, 4*i+1);
    split_store(v.z, g_xh, g_xl, 4*i+2); split_store(v.w, g_xh, g_xl, 4*i+3);
}

// ---------------- 1) router ----------------
__global__ void router_kernel(const float* __restrict__ x,
                              const float* __restrict__ wqkv) {
    __shared__ float sx[Hdim];
    __shared__ float sdot[24];
    const int t = blockIdx.x;
    const float* xr = x + (size_t)t * Hdim;
    for (int i = threadIdx.x; i < Hdim; i += blockDim.x) sx[i] = xr[i];
    __syncthreads();
    const int warp = threadIdx.x >> 5, lane = threadIdx.x & 31;
    for (int o = warp; o < 24; o += 8) {
        const float* w = wqkv + (size_t)o * Hdim;
        float s = 0.f;
        for (int i = lane; i < Hdim; i += 32) s += sx[i] * w[i];
        #pragma unroll
        for (int off = 16; off; off >>= 1) s += __shfl_down_sync(0xffffffffu, s, off);
        if (lane == 0) sdot[o] = s;
    }
    __syncthreads();
    if (threadIdx.x == 0) {
        float q[NEXP], k[NEXP], v[NEXP], logit[NEXP];
        #pragma unroll
        for (int e = 0; e < NEXP; e++) { q[e]=sdot[e]; k[e]=sdot[8+e]; v[e]=sdot[16+e]; }
        for (int e = 0; e < NEXP; e++) {
            float m = -1e30f;
            for (int j = 0; j < NEXP; j++) m = fmaxf(m, q[e]*k[j]);
            float se = 0.f, acc = 0.f;
            for (int j = 0; j < NEXP; j++) {
                float ex = expf(q[e]*k[j] - m);
                se += ex; acc += ex * v[j];
            }
            logit[e] = acc / se;
        }
        int i0 = 0;
        for (int j = 1; j < NEXP; j++) if (logit[j] > logit[i0]) i0 = j;
        int i1 = -1;
        for (int j = 0; j < NEXP; j++) {
            if (j == i0) continue;
            if (i1 < 0 || logit[j] > logit[i1]) i1 = j;
        }
        float e1 = expf(logit[i1] - logit[i0]);
        float inv = 1.f / (1.f + e1);
        g_pair_expert[2*t]   = i0; g_pair_score[2*t]   = inv;
        g_pair_expert[2*t+1] = i1; g_pair_score[2*t+1] = e1 * inv;
    }
}

// ---------------- 2) scheduling ----------------
__global__ void schedule_kernel() {
    __shared__ int s_cnt[NEXP], s_off[NEXP], s_cur[NEXP];
    const int tid = threadIdx.x;
    if (tid < NEXP) { s_cnt[tid] = 0; s_cur[tid] = 0; }
    __syncthreads();
    for (int i = tid; i < MAX_ROWS; i += blockDim.x) g_row_map[i] = -1;
    for (int p = tid; p < NPAIR; p += blockDim.x)
        atomicAdd(&s_cnt[g_pair_expert[p]], 1);
    __syncthreads();
    if (tid == 0) {
        int off = 0, t = 0;
        for (int e = 0; e < NEXP; e++) {
            s_off[e] = off;
            int nt = (s_cnt[e] + BM - 1) / BM;
            for (int i = 0; i < nt; i++) g_tile_expert[t++] = e;
            off += nt * BM;
        }
        for (; t < MAX_TILES; t++) g_tile_expert[t] = -1;
    }
    __syncthreads();
    for (int p = tid; p < NPAIR; p += blockDim.x) {
        int e = g_pair_expert[p];
        int pos = atomicAdd(&s_cur[e], 1);
        g_row_map[s_off[e] + pos] = p;
    }
}

// ---------------- 3) FFN1 GEMM: h1 = x @ w1[e]^T (bf16x3, HMMA) ----------------
__global__ void __launch_bounds__(256,1) ffn1_kernel(){
    extern __shared__ char sm[];
    const int tileRow = blockIdx.y;
    const int e = g_tile_expert[tileRow];
    if (e < 0) return;
    const int f0   = blockIdx.x * BN;
    const int base = tileRow * BM;
    const int tid  = threadIdx.x;
    const int wid  = tid >> 5, lane = tid & 31;
    const int wm = wid >> 2, wn = wid & 3;         // 2 x 4 warps
    const uint32_t su = smem_u32(sm);
    int* s_p = (int*)sm;

    if (tid < BM) s_p[tid] = g_row_map[base + tid];
    __syncthreads();

    // lane-dependent ldmatrix offsets
    const int r8 = lane & 7, m2 = (lane >> 3) & 3;
    const uint32_t aOff = (uint32_t)(r8 + (m2 & 1)*8)*ROWB + (uint32_t)(m2 >> 1)*16;
    const uint32_t bOff = (uint32_t)(r8 + (m2 >> 1)*8)*ROWB + (uint32_t)(m2 & 1)*16;

    const size_t wb = (size_t)e * NCOL1 * Hdim;
    float c[4][4][4];
    #pragma unroll
    for (int a = 0; a < 4; a++)
        #pragma unroll
        for (int b = 0; b < 4; b++)
            #pragma unroll
            for (int d = 0; d < 4; d++) c[a][b][d] = 0.f;

    load_stage_g(su, 0, 0, s_p, g_xh, g_xl, 1, Hdim, g_w1h, g_w1l, wb, f0, Hdim, tid); CPCOMMIT();
    load_stage_g(su, 1, 1, s_p, g_xh, g_xl, 1, Hdim, g_w1h, g_w1l, wb, f0, Hdim, tid); CPCOMMIT();

    for (int kb = 0; kb < NKB1; kb++){
        CPWAIT1();
        __syncthreads();
        if (kb + 2 < NKB1){
            load_stage_g(su, (kb+2)%NSTAGE, kb+2, s_p, g_xh, g_xl, 1, Hdim,
                         g_w1h, g_w1l, wb, f0, Hdim, tid);
            CPCOMMIT();
        }
        compute_stage(su + 512 + (kb%NSTAGE)*STAGEB, c, aOff, bOff, wm, wn);
    }

    // epilogue -> fp32 g_h1
    const int l4 = lane >> 2, l2 = (lane & 3)*2;
    #pragma unroll
    for (int mi = 0; mi < 4; mi++){
        int r0 = wm*64 + mi*16 + l4;
        int p0 = s_p[r0], p1 = s_p[r0 + 8];
        #pragma unroll
        for (int nj = 0; nj < 4; nj++){
            int col = f0 + wn*32 + nj*8 + l2;
            if (p0 >= 0){
                float2 v = make_float2(c[mi][nj][0], c[mi][nj][1]);
                *(float2*)&g_h1[(size_t)p0*NCOL1 + col] = v;
            }
            if (p1 >= 0){
                float2 v = make_float2(c[mi][nj][2], c[mi][nj][3]);
                *(float2*)&g_h1[(size_t)p1*NCOL1 + col] = v;
            }
        }
    }
}

// ---------------- 4) silu(a)*g -> bf16 hi/lo activations ----------------
__global__ void silu_kernel(){
    size_t i = (size_t)blockIdx.x*blockDim.x + threadIdx.x;
    size_t n2 = (size_t)NPAIR*Fdim/2;
    if (i >= n2) return;
    size_t p = i / (Fdim/2);
    int f = (int)(i % (Fdim/2)) * 2;
    const float2 a2 = *(const float2*)&g_h1[p*NCOL1 + f];
    const float2 g2 = *(const float2*)&g_h1[p*NCOL1 + Fdim + f];
    float o0 = (a2.x / (1.f + expf(-a2.x))) * g2.x;
    float o1 = (a2.y / (1.f + expf(-a2.y))) * g2.y;
    __nv_bfloat16 h0 = __float2bfloat16(o0), h1 = __float2bfloat16(o1);
    __nv_bfloat16 l0 = __float2bfloat16(o0 - __bfloat162float(h0));
    __nv_bfloat16 l1 = __float2bfloat16(o1 - __bfloat162float(h1));
    *(__nv_bfloat162*)(g_acth + p*Fdim + f) = __halves2bfloat162(h0, h1);
    *(__nv_bfloat162*)(g_actl + p*Fdim + f) = __halves2bfloat162(l0, l1);
}

// ---------------- 5) FFN2 GEMM: out = act @ w2[e]^T, scaled ----------------
__global__ void __launch_bounds__(256,1) ffn2_kernel(){
    extern __shared__ char sm[];
    const int tileRow = blockIdx.y;
    const int e = g_tile_expert[tileRow];
    if (e < 0) return;
    const int n0   = blockIdx.x * BN;
    const int base = tileRow * BM;
    const int tid  = threadIdx.x;
    const int wid  = tid >> 5, lane = tid & 31;
    const int wm = wid >> 2, wn = wid & 3;
    const uint32_t su = smem_u32(sm);
    int* s_p = (int*)sm;

    if (tid < BM) s_p[tid] = g_row_map[base + tid];
    __syncthreads();

    const int r8 = lane & 7, m2 = (lane >> 3) & 3;
    const uint32_t aOff = (uint32_t)(r8 + (m2 & 1)*8)*ROWB + (uint32_t)(m2 >> 1)*16;
    const uint32_t bOff = (uint32_t)(r8 + (m2 >> 1)*8)*ROWB + (uint32_t)(m2 & 1)*16;

    const size_t wb = (size_t)e * Hdim * Fdim;
    float c[4][4][4];
    #pragma unroll
    for (int a = 0; a < 4; a++)
        #pragma unroll
        for (int b = 0; b < 4; b++)
            #pragma unroll
            for (int d = 0; d < 4; d++) c[a][b][d] = 0.f;

    load_stage_g(su, 0, 0, s_p, g_acth, g_actl, 0, Fdim, g_w2h, g_w2l, wb, n0, Fdim, tid); CPCOMMIT();
    load_stage_g(su, 1, 1, s_p, g_acth, g_actl, 0, Fdim, g_w2h, g_w2l, wb, n0, Fdim, tid); CPCOMMIT();

    for (int kb = 0; kb < NKB2; kb++){
        CPWAIT1();
        __syncthreads();
        if (kb + 2 < NKB2){
            load_stage_g(su, (kb+2)%NSTAGE, kb+2, s_p, g_acth, g_actl, 0, Fdim,
                         g_w2h, g_w2l, wb, n0, Fdim, tid);
            CPCOMMIT();
        }
        compute_stage(su + 512 + (kb%NSTAGE)*STAGEB, c, aOff, bOff, wm, wn);
    }

    const int l4 = lane >> 2, l2 = (lane & 3)*2;
    #pragma unroll
    for (int mi = 0; mi < 4; mi++){
        int r0 = wm*64 + mi*16 + l4;
        int p0 = s_p[r0], p1 = s_p[r0 + 8];
        float sc0 = (p0 >= 0) ? g_pair_score[p0] : 0.f;
        float sc1 = (p1 >= 0) ? g_pair_score[p1] : 0.f;
        #pragma unroll
        for (int nj = 0; nj < 4; nj++){
            int col = n0 + wn*32 + nj*8 + l2;
            if (p0 >= 0){
                float2 v = make_float2(c[mi][nj][0]*sc0, c[mi][nj][1]*sc0);
                *(float2*)&g_outp[(size_t)p0*Hdim + col] = v;
            }
            if (p1 >= 0){
                float2 v = make_float2(c[mi][nj][2]*sc1, c[mi][nj][3]*sc1);
                *(float2*)&g_outp[(size_t)p1*Hdim + col] = v;
            }
        }
    }
}

// ---------------- 6) combine ----------------
__global__ void combine_kernel(float* __restrict__ out) {
    int i = blockIdx.x * blockDim.x + threadIdx.x;
    if (i >= NTOK * Hdim) return;
    int t = i >> 10;
    int j = i & 1023;
    out[i] = g_outp[(size_t)(2*t) * Hdim + j] + g_outp[(size_t)(2*t+1) * Hdim + j];
}

// ---------------- launch ----------------
extern "C" void kernel_launch(void* const* d_in, const int* in_sizes, int n_in,
                              void* d_out, int out_size) {
    const float* x    = (const float*)d_in[0];
    const float* wqkv = (const float*)d_in[1];
    const float* w1   = (const float*)d_in[2];
    const float* w2   = (const float*)d_in[3];
    float* out = (float*)d_out;

    cudaFuncSetAttribute(ffn1_kernel, cudaFuncAttributeMaxDynamicSharedMemorySize, SMEM_TOT);
    cudaFuncSetAttribute(ffn2_kernel, cudaFuncAttributeMaxDynamicSharedMemorySize, SMEM_TOT);

    router_kernel<<<NTOK, 256>>>(x, wqkv);
    schedule_kernel<<<1, 256>>>();

    split_x_kernel<<<(NTOK*Hdim/4 + 255)/256, 256>>>((const float4*)x);
    split_w1_kernel<<<(int)(((size_t)NEXP*NCOL1*Hdim/4 + 255)/256), 256>>>((const float4*)w1);
    split_w2_kernel<<<(int)(((size_t)NEXP*Hdim*Fdim/4 + 255)/256), 256>>>((const float4*)w2);

    dim3 g1(NCOL1 / BN, MAX_TILES);   // (44, 72)
    ffn1_kernel<<<g1, 256, SMEM_TOT>>>();
    silu_kernel<<<(int)(((size_t)NPAIR*Fdim/2 + 255)/256), 256>>>();
    dim3 g2(Hdim / BN, MAX_TILES);    // (8, 72)
    ffn2_kernel<<<g2, 256, SMEM_TOT>>>();
    combine_kernel<<<(NTOK * Hdim + 255) / 256, 256>>>(out);
}